// round 14
// baseline (speedup 1.0000x reference)
#include <cuda_runtime.h>
#include <cuda_bf16.h>
#include <math.h>

typedef unsigned long long ull;
typedef unsigned int uint;

#define NPTS 100000
#define BQ 500
#define KNN 100
#define C1 128
#define C2 1024
#define ROWS_TOT (BQ*KNN)
#define GD 64
#define GD3 (GD*GD*GD)
#define BCAP 512

// ---------------- scratch (device globals; no cudaMalloc allowed) ----------------
__device__ unsigned g_bbmin[3], g_bbmax[3];
__device__ float g_orig[3], g_w, g_winv;
__device__ int   g_cellcnt[GD3];
__device__ int   g_cellstart[GD3+1];
__device__ int   g_cellfill[GD3];
__device__ int   g_blocksum[256];
__device__ int   g_blockoff[257];
__device__ float4 g_spts[NPTS];
__device__ int   g_nbr[BQ*KNN];
__device__ uint  g_h1s[ROWS_TOT*C1];     // packed bf16: hi | (lo<<16)
__device__ uint  g_wfH[65536];           // W frag pool hi: [ot][ph][e]
__device__ uint  g_wfL[65536];           // W frag pool lo
__device__ float g_psum[BQ*C2];
__device__ float g_psumsq[BQ*C2];
__device__ float g_gmax[BQ*C2];
__device__ float g_gmin[BQ*C2];
__device__ float g_s1[C2], g_t1[C2];
__device__ float g_feat0[BQ*C2];
__device__ float g_z1[BQ*512];
__device__ float g_z2[BQ*256];
__device__ float g_s4[512], g_t4[512];
__device__ float g_s5[256], g_t5[256];

// ============================ grid build ============================
__device__ __forceinline__ unsigned enc_f(float f) {
    unsigned b = __float_as_uint(f);
    return (b & 0x80000000u) ? ~b : (b | 0x80000000u);
}
__device__ __forceinline__ float dec_f(unsigned u) {
    unsigned b = (u & 0x80000000u) ? (u ^ 0x80000000u) : ~u;
    return __uint_as_float(b);
}

__global__ void zero_init_kernel() {
    int i = blockIdx.x*256 + threadIdx.x;
    if (i < GD3) g_cellcnt[i] = 0;
    if (i < 3) { g_bbmin[i] = 0xFFFFFFFFu; g_bbmax[i] = 0u; }
}

__global__ __launch_bounds__(256) void bbox_kernel(const float* __restrict__ pts) {
    __shared__ unsigned smin[3][32], smax[3][32];
    unsigned lmin[3] = {0xFFFFFFFFu,0xFFFFFFFFu,0xFFFFFFFFu};
    unsigned lmax[3] = {0,0,0};
    for (int i = blockIdx.x*256 + threadIdx.x; i < NPTS; i += gridDim.x*256) {
        #pragma unroll
        for (int a = 0; a < 3; a++) {
            unsigned e = enc_f(pts[i*3+a]);
            lmin[a] = min(lmin[a], e); lmax[a] = max(lmax[a], e);
        }
    }
    int lane = threadIdx.x & 31, w = threadIdx.x >> 5;
    #pragma unroll
    for (int a = 0; a < 3; a++) {
        #pragma unroll
        for (int o = 16; o; o >>= 1) {
            lmin[a] = min(lmin[a], __shfl_xor_sync(0xFFFFFFFFu, lmin[a], o));
            lmax[a] = max(lmax[a], __shfl_xor_sync(0xFFFFFFFFu, lmax[a], o));
        }
        if (lane == 0) { smin[a][w] = lmin[a]; smax[a][w] = lmax[a]; }
    }
    __syncthreads();
    if (threadIdx.x < 3) {
        int a = threadIdx.x;
        unsigned mn = 0xFFFFFFFFu, mx = 0;
        for (int i = 0; i < 8; i++) { mn = min(mn, smin[a][i]); mx = max(mx, smax[a][i]); }
        atomicMin(&g_bbmin[a], mn);
        atomicMax(&g_bbmax[a], mx);
    }
}

__global__ void bbox_fin_kernel() {
    if (threadIdx.x == 0) {
        float rmax = 0.f;
        for (int a = 0; a < 3; a++) {
            float mn = dec_f(g_bbmin[a]), mx = dec_f(g_bbmax[a]);
            g_orig[a] = mn;
            rmax = fmaxf(rmax, mx - mn);
        }
        float w = rmax / (float)GD * 1.000002f + 1e-12f;
        g_w = w; g_winv = 1.f / w;
    }
}

__device__ __forceinline__ int cell_of(float x, float ox, float winv) {
    int i = (int)((x - ox) * winv);
    return min(max(i, 0), GD-1);
}

__global__ void grid_count_kernel(const float* __restrict__ pts) {
    int i = blockIdx.x*256 + threadIdx.x;
    if (i >= NPTS) return;
    float wi = g_winv;
    int ix = cell_of(pts[i*3+0], g_orig[0], wi);
    int iy = cell_of(pts[i*3+1], g_orig[1], wi);
    int iz = cell_of(pts[i*3+2], g_orig[2], wi);
    atomicAdd(&g_cellcnt[(iz*GD+iy)*GD+ix], 1);
}

__global__ __launch_bounds__(256) void prefixA_kernel() {
    __shared__ int red[256];
    int bk = blockIdx.x, t = threadIdx.x;
    int base = bk*1024 + t*4;
    int s = g_cellcnt[base] + g_cellcnt[base+1] + g_cellcnt[base+2] + g_cellcnt[base+3];
    red[t] = s; __syncthreads();
    for (int st = 128; st; st >>= 1) { if (t < st) red[t] += red[t+st]; __syncthreads(); }
    if (t == 0) g_blocksum[bk] = red[0];
}

__global__ __launch_bounds__(256) void prefixB_kernel() {
    __shared__ int sc[256];
    int t = threadIdx.x;
    sc[t] = g_blocksum[t]; __syncthreads();
    for (int off = 1; off < 256; off <<= 1) {
        int v = (t >= off) ? sc[t-off] : 0;
        __syncthreads();
        sc[t] += v;
        __syncthreads();
    }
    g_blockoff[t+1] = sc[t];
    if (t == 0) g_blockoff[0] = 0;
}

__global__ __launch_bounds__(256) void prefixC_kernel() {
    __shared__ int sc[256];
    int bk = blockIdx.x, t = threadIdx.x;
    int base = bk*1024 + t*4;
    int c0 = g_cellcnt[base], c1 = g_cellcnt[base+1], c2 = g_cellcnt[base+2], c3 = g_cellcnt[base+3];
    int tot = c0+c1+c2+c3;
    sc[t] = tot; __syncthreads();
    for (int off = 1; off < 256; off <<= 1) {
        int v = (t >= off) ? sc[t-off] : 0;
        __syncthreads();
        sc[t] += v;
        __syncthreads();
    }
    int run = g_blockoff[bk] + sc[t] - tot;
    g_cellstart[base] = run;   g_cellfill[base] = run;   run += c0;
    g_cellstart[base+1] = run; g_cellfill[base+1] = run; run += c1;
    g_cellstart[base+2] = run; g_cellfill[base+2] = run; run += c2;
    g_cellstart[base+3] = run; g_cellfill[base+3] = run;
    if (bk == 255 && t == 255) g_cellstart[GD3] = g_blockoff[256];
}

__global__ void scatter_kernel(const float* __restrict__ pts) {
    int i = blockIdx.x*256 + threadIdx.x;
    if (i >= NPTS) return;
    float x = pts[i*3+0], y = pts[i*3+1], z = pts[i*3+2];
    float wi = g_winv;
    int ix = cell_of(x, g_orig[0], wi);
    int iy = cell_of(y, g_orig[1], wi);
    int iz = cell_of(z, g_orig[2], wi);
    int pos = atomicAdd(&g_cellfill[(iz*GD+iy)*GD+ix], 1);
    if (pos >= 0 && pos < NPTS) g_spts[pos] = make_float4(x, y, z, __int_as_float(i));
}

// ============================ grid kNN (exact, L-inf) ============================
__constant__ int c_msched[13] = {0,1,2,3,4,6,8,11,16,22,31,44,63};

__global__ __launch_bounds__(256) void knn_grid_kernel(const float* __restrict__ pts,
                                                       const int* __restrict__ index)
{
    __shared__ unsigned hist[4096];
    __shared__ float bd_d[BCAP];
    __shared__ int   bd_i[BCAP];
    __shared__ int scnt[256];
    __shared__ int wred[8];
    __shared__ int s_T, s_cl, s_loPos, s_bdc, s_selc;
    __shared__ float qx, qy, qz;

    int b = blockIdx.x, tid = threadIdx.x;
    if (tid == 0) {
        int n = index[b];
        qx = pts[n*3+0]; qy = pts[n*3+1]; qz = pts[n*3+2];
    }
    for (int i = tid; i < 4096; i += 256) hist[i] = 0u;
    __syncthreads();

    float wi = g_winv;
    int cx = cell_of(qx, g_orig[0], wi);
    int cy = cell_of(qy, g_orig[1], wi);
    int cz = cell_of(qz, g_orig[2], wi);
    int wid = tid >> 5, lane = tid & 31;

    int m = 0;
    for (int si = 0; si < 13; si++) {
        m = c_msched[si];
        int zlo = max(cz-m,0), zhi = min(cz+m,GD-1);
        int ylo = max(cy-m,0), yhi = min(cy+m,GD-1);
        int xlo = max(cx-m,0), xhi = min(cx+m,GD-1);
        int yext = yhi-ylo+1;
        int R = (zhi-zlo+1)*yext;
        int cnt = 0;
        for (int r = tid; r < R; r += 256) {
            int z = zlo + r/yext, y = ylo + r%yext;
            int base = (z*GD+y)*GD;
            cnt += g_cellstart[base+xhi+1] - g_cellstart[base+xlo];
        }
        #pragma unroll
        for (int o = 16; o; o >>= 1) cnt += __shfl_xor_sync(0xFFFFFFFFu, cnt, o);
        if (lane == 0) wred[wid] = cnt;
        __syncthreads();
        if (tid == 0) {
            int s = 0;
            #pragma unroll
            for (int i = 0; i < 8; i++) s += wred[i];
            wred[0] = s;
        }
        __syncthreads();
        int total = wred[0];
        __syncthreads();
        bool full = (zlo==0 && zhi==GD-1 && ylo==0 && yhi==GD-1 && xlo==0 && xhi==GD-1);
        if (total >= KNN || full) break;
    }
    int mh = m + 1;
    int zlo = max(cz-mh,0), zhi = min(cz+mh,GD-1);
    int ylo = max(cy-mh,0), yhi = min(cy+mh,GD-1);
    int xlo = max(cx-mh,0), xhi = min(cx+mh,GD-1);
    int yext = yhi-ylo+1;
    int R = (zhi-zlo+1)*yext;

    for (int r = wid; r < R; r += 8) {
        int z = zlo + r/yext, y = ylo + r%yext;
        int base = (z*GD+y)*GD;
        int lo = g_cellstart[base+xlo], hi = g_cellstart[base+xhi+1];
        lo = min(max(lo, 0), NPTS); hi = min(max(hi, lo), NPTS);
        for (int t = lo + lane; t < hi; t += 32) {
            float4 p = g_spts[t];
            float d = fmaxf(fmaxf(fabsf(p.x-qx), fabsf(p.y-qy)), fabsf(p.z-qz));
            unsigned bin = __float_as_uint(d) >> 19;
            if (bin > 4095u) bin = 4095u;
            atomicAdd(&hist[bin], 1u);
        }
    }
    __syncthreads();

    {
        unsigned s = 0;
        #pragma unroll
        for (int j = 0; j < 16; j++) s += hist[tid*16 + j];
        scnt[tid] = (int)s;
    }
    __syncthreads();
    if (tid == 0) {
        int cum = 0, si = 0;
        while (si < 255 && cum + scnt[si] < KNN) { cum += scnt[si]; si++; }
        int t = si*16;
        for (; t < 4095; t++) {
            int h = (int)hist[t];
            if (cum + h >= KNN) break;
            cum += h;
        }
        s_T = t; s_cl = cum;
        s_loPos = 0; s_bdc = 0; s_selc = cum;
    }
    __syncthreads();
    int T = s_T, cl = s_cl;

    for (int r = wid; r < R; r += 8) {
        int z = zlo + r/yext, y = ylo + r%yext;
        int base = (z*GD+y)*GD;
        int lo = g_cellstart[base+xlo], hi = g_cellstart[base+xhi+1];
        lo = min(max(lo, 0), NPTS); hi = min(max(hi, lo), NPTS);
        for (int t = lo + lane; t < hi; t += 32) {
            float4 p = g_spts[t];
            float d = fmaxf(fmaxf(fabsf(p.x-qx), fabsf(p.y-qy)), fabsf(p.z-qz));
            unsigned bin = __float_as_uint(d) >> 19;
            if (bin > 4095u) bin = 4095u;
            int bi = (int)bin;
            if (bi < T) {
                int ppos = atomicAdd(&s_loPos, 1);
                if (ppos < KNN) g_nbr[b*KNN + ppos] = __float_as_int(p.w);
            } else if (bi == T) {
                int ppos = atomicAdd(&s_bdc, 1);
                if (ppos < BCAP) { bd_d[ppos] = d; bd_i[ppos] = __float_as_int(p.w); }
            }
        }
    }
    __syncthreads();

    int need = KNN - cl;
    int c = s_bdc < BCAP ? s_bdc : BCAP;
    for (int i = tid; i < c; i += 256) {
        float di = bd_d[i];
        int   ni = bd_i[i];
        int rank = 0;
        for (int j = 0; j < c; j++) {
            float dj = bd_d[j];
            rank += (dj < di) || (dj == di && bd_i[j] < ni);
        }
        if (rank < need) {
            int pp = atomicAdd(&s_selc, 1);
            if (pp < KNN) g_nbr[b*KNN + pp] = ni;
        }
    }
}

// ============================ bf16 helpers ============================
__device__ __forceinline__ unsigned short bf16_bits(float f) {
    __nv_bfloat16 h = __float2bfloat16(f);
    return *reinterpret_cast<unsigned short*>(&h);
}
__device__ __forceinline__ float bf16_val(unsigned short u) {
    __nv_bfloat16 h = *reinterpret_cast<__nv_bfloat16*>(&u);
    return __bfloat162float(h);
}

// ============================ KPConv (emits packed hi|lo bf16) ============================
__global__ __launch_bounds__(128) void kpconv_kernel(const float* __restrict__ pts,
                                                     const float* __restrict__ kp_points,
                                                     const float* __restrict__ kp_weights,
                                                     const float* __restrict__ kp_sigma,
                                                     const int* __restrict__ index)
{
    __shared__ float kpw_s[48*128];
    __shared__ float v_s[100*48];
    __shared__ float rel_s[100][3];
    __shared__ float w_s[100][16];
    __shared__ float sel[3];
    __shared__ float kpp_s[15][3];

    int b = blockIdx.x;
    int tid = threadIdx.x;

    for (int idx = tid; idx < 48*128; idx += 128) {
        int j = idx >> 7, o = idx & 127;
        kpw_s[idx] = (j < 45) ? kp_weights[j*128 + o] : 0.f;
    }
    if (tid < 3) sel[tid] = pts[(long)index[b]*3 + tid];
    if (tid < 45) kpp_s[tid/3][tid%3] = kp_points[tid];
    __syncthreads();

    if (tid < 100) {
        int n = g_nbr[b*KNN + tid];
        n = min(max(n, 0), NPTS-1);
        rel_s[tid][0] = pts[n*3+0] - sel[0];
        rel_s[tid][1] = pts[n*3+1] - sel[1];
        rel_s[tid][2] = pts[n*3+2] - sel[2];
    }
    __syncthreads();

    float sg = kp_sigma[0];
    float inv2 = -0.5f / (sg*sg);

    for (int idx = tid; idx < 100*16; idx += 128) {
        int k = idx >> 4, p = idx & 15;
        float val = 0.f;
        if (p < 15) {
            float dx = rel_s[k][0] - kpp_s[p][0];
            float dy = rel_s[k][1] - kpp_s[p][1];
            float dz = rel_s[k][2] - kpp_s[p][2];
            val = __expf(inv2 * (dx*dx + dy*dy + dz*dz));
        }
        w_s[k][p] = val;
    }
    __syncthreads();

    for (int idx = tid; idx < 100*48; idx += 128) {
        int k = idx / 48, j = idx - k*48;
        float val = 0.f;
        if (j < 45) {
            int p = j / 3, ch = j - p*3;
            val = rel_s[k][ch] * w_s[k][p];
        }
        v_s[idx] = val;
    }
    __syncthreads();

    int o = tid;
    float kw[48];
    #pragma unroll
    for (int j = 0; j < 48; j++) kw[j] = kpw_s[j*128 + o];

    for (int k = 0; k < KNN; k++) {
        const float4* vp = (const float4*)&v_s[k*48];
        float a0 = 0.f, a1 = 0.f, a2 = 0.f, a3 = 0.f;
        #pragma unroll
        for (int j4 = 0; j4 < 12; j4++) {
            float4 v4 = vp[j4];
            a0 += v4.x * kw[j4*4+0];
            a1 += v4.y * kw[j4*4+1];
            a2 += v4.z * kw[j4*4+2];
            a3 += v4.w * kw[j4*4+3];
        }
        float v = fmaxf((a0+a1) + (a2+a3), 0.f);
        unsigned short hi = bf16_bits(v);
        unsigned short lo = bf16_bits(v - bf16_val(hi));
        g_h1s[(b*KNN + k)*C1 + o] = (uint)hi | ((uint)lo << 16);
    }
}

// ============ W fragment precompute (once; frag-ordered global pools) ============
__global__ void wprep_kernel(const float* __restrict__ W) {
    int e2 = blockIdx.x*256 + threadIdx.x;
    if (e2 >= 65536) return;
    int ot = e2 >> 13, rem = e2 & 8191;
    int ph = rem >> 12, e = rem & 4095;
    int R = e & 1, L = (e >> 1) & 31, N = (e >> 6) & 15, K = e >> 10;
    int n = N*8 + (L >> 2);
    int k = ph*64 + K*16 + (L & 3)*2 + R*8;
    const float* wp = &W[((size_t)(ot*128 + n))*C1 + k];
    float f0 = wp[0], f1 = wp[1];
    unsigned short h0 = bf16_bits(f0), h1 = bf16_bits(f1);
    g_wfH[e2] = (uint)h0 | ((uint)h1 << 16);
    unsigned short l0 = bf16_bits(f0 - bf16_val(h0));
    unsigned short l1 = bf16_bits(f1 - bf16_val(h1));
    g_wfL[e2] = (uint)l0 | ((uint)l1 << 16);
}

// ======== conv1 v10: v8 + warp owns 2 m-tiles x 8 n-tiles (halves B LDS) ========
#define OFF_AL   16384
#define OFF_WH   32768
#define OFF_WL   49152
#define OFF_PART 66560
#define OFF_BIAS 70656
#define CONV1_SMEM 71168
#define STG_LD 130

__global__ __launch_bounds__(256, 2) void conv1_kernel(const float* __restrict__ bias)
{
    extern __shared__ char smc[];
    uint* AH = (uint*)smc;
    uint* AL = (uint*)(smc + OFF_AL);
    uint* WH = (uint*)(smc + OFF_WH);
    uint* WL = (uint*)(smc + OFF_WL);
    float* sbias = (float*)(smc + OFF_BIAS);

    int ot = blockIdx.x, b = blockIdx.y;
    int tid = threadIdx.x, lane = tid & 31, wid = tid >> 5;
    int mset = wid & 3, nh = wid >> 2;

    if (tid < 128) sbias[tid] = bias[ot*128 + tid];

    // acc[m-tile local][n-tile local][reg]
    float acc[2][8][4];
    #pragma unroll
    for (int i = 0; i < 2; i++)
        #pragma unroll
        for (int j = 0; j < 8; j++)
            #pragma unroll
            for (int r = 0; r < 4; r++) acc[i][j][r] = 0.f;

    for (int ph = 0; ph < 2; ph++) {
        if (ph) __syncthreads();

        // ---- A pack: 2 LDG.32 + bit-permute per element (unchanged from v8) ----
        for (int e = tid; e < 4096; e += 256) {
            int R = e & 3, L = (e >> 2) & 31, M = (e >> 7) & 7, K = e >> 10;
            int row = M*16 + (L >> 2) + (R & 1)*8;
            int k   = ph*64 + K*16 + (L & 3)*2 + ((R >> 1) & 1)*8;
            uint s0 = 0, s1 = 0;
            if (row < KNN) {
                const uint* hp = &g_h1s[((size_t)b*KNN + row)*C1 + k];
                s0 = hp[0]; s1 = hp[1];
            }
            AH[e] = (s0 & 0xFFFFu) | (s1 << 16);
            AL[e] = (s0 >> 16) | (s1 & 0xFFFF0000u);
        }
        // ---- W fill: straight uint4 copy from precomputed pools ----
        {
            int wbase = (ot*2 + ph) << 12;
            const uint4* srcH = (const uint4*)&g_wfH[wbase];
            const uint4* srcL = (const uint4*)&g_wfL[wbase];
            uint4* dstH = (uint4*)WH;
            uint4* dstL = (uint4*)WL;
            for (int i = tid; i < 1024; i += 256) {
                dstH[i] = srcH[i];
                dstL[i] = srcL[i];
            }
        }
        __syncthreads();

        // ---- MMA: warp owns m-tiles {2*mset, 2*mset+1}, n-tiles nh*8..+8 ----
        #pragma unroll
        for (int p = 0; p < 3; p++) {
            const uint* Ab = (p == 1) ? AL : AH;
            const uint* Bb = (p == 2) ? WL : WH;
            #pragma unroll
            for (int ks = 0; ks < 4; ks++) {
                uint4 a0 = *(const uint4*)&Ab[(((ks*8 + mset*2 + 0)*32) + lane)*4];
                uint4 a1 = *(const uint4*)&Ab[(((ks*8 + mset*2 + 1)*32) + lane)*4];
                #pragma unroll
                for (int j = 0; j < 8; j++) {
                    int nt = nh*8 + j;
                    uint2 bf = *(const uint2*)&Bb[(((ks*16 + nt)*32) + lane)*2];
                    asm volatile(
                        "mma.sync.aligned.m16n8k16.row.col.f32.bf16.bf16.f32 "
                        "{%0,%1,%2,%3}, {%4,%5,%6,%7}, {%8,%9}, {%0,%1,%2,%3};"
                        : "+f"(acc[0][j][0]), "+f"(acc[0][j][1]), "+f"(acc[0][j][2]), "+f"(acc[0][j][3])
                        : "r"(a0.x), "r"(a0.y), "r"(a0.z), "r"(a0.w), "r"(bf.x), "r"(bf.y));
                    asm volatile(
                        "mma.sync.aligned.m16n8k16.row.col.f32.bf16.bf16.f32 "
                        "{%0,%1,%2,%3}, {%4,%5,%6,%7}, {%8,%9}, {%0,%1,%2,%3};"
                        : "+f"(acc[1][j][0]), "+f"(acc[1][j][1]), "+f"(acc[1][j][2]), "+f"(acc[1][j][3])
                        : "r"(a1.x), "r"(a1.y), "r"(a1.z), "r"(a1.w), "r"(bf.x), "r"(bf.y));
                }
            }
        }
    }
    __syncthreads();

    // ---- stage relu(D + bias) into smem [col][row] (reuses frag space) ----
    float* stage = (float*)smc;
    {
        int g = lane >> 2, tg = lane & 3;
        #pragma unroll
        for (int i = 0; i < 2; i++) {
            int r0 = (mset*2 + i)*16 + g, r1 = r0 + 8;
            #pragma unroll
            for (int j = 0; j < 8; j++) {
                int c0 = nh*64 + j*8 + tg*2;
                stage[c0*STG_LD + r0]     = fmaxf(acc[i][j][0] + sbias[c0], 0.f);
                stage[(c0+1)*STG_LD + r0] = fmaxf(acc[i][j][1] + sbias[c0+1], 0.f);
                stage[c0*STG_LD + r1]     = fmaxf(acc[i][j][2] + sbias[c0], 0.f);
                stage[(c0+1)*STG_LD + r1] = fmaxf(acc[i][j][3] + sbias[c0+1], 0.f);
            }
        }
    }
    __syncthreads();

    // ---- column stats over rows 0..99 (2 threads per column) ----
    float* part = (float*)(smc + OFF_PART);
    {
        int col = tid >> 1, half = tid & 1;
        float mx = -1e30f, mn = 1e30f, s = 0.f, q = 0.f;
        int rbeg = half*50;
        #pragma unroll 10
        for (int r = rbeg; r < rbeg + 50; r++) {
            float v = stage[col*STG_LD + r];
            mx = fmaxf(mx, v); mn = fminf(mn, v);
            s += v; q += v*v;
        }
        part[0*256 + tid] = mx;
        part[1*256 + tid] = mn;
        part[2*256 + tid] = s;
        part[3*256 + tid] = q;
    }
    __syncthreads();
    if (tid < 128) {
        int e = tid*2;
        int o = b*C2 + ot*128 + tid;
        g_gmax[o]   = fmaxf(part[0*256 + e], part[0*256 + e + 1]);
        g_gmin[o]   = fminf(part[1*256 + e], part[1*256 + e + 1]);
        g_psum[o]   = part[2*256 + e] + part[2*256 + e + 1];
        g_psumsq[o] = part[3*256 + e] + part[3*256 + e + 1];
    }
}

// ============================ BN1 stats (parallel) ============================
__global__ __launch_bounds__(128) void bn1_stats_kernel(const float* __restrict__ g,
                                                        const float* __restrict__ bet)
{
    __shared__ double ss[128], sq[128];
    int o = blockIdx.x, t = threadIdx.x;
    double s = 0.0, q = 0.0;
    for (int b = t; b < BQ; b += 128) {
        s += (double)g_psum[b*C2 + o];
        q += (double)g_psumsq[b*C2 + o];
    }
    ss[t] = s; sq[t] = q; __syncthreads();
    for (int st = 64; st; st >>= 1) {
        if (t < st) { ss[t] += ss[t+st]; sq[t] += sq[t+st]; }
        __syncthreads();
    }
    if (t == 0) {
        double mean = ss[0] / (double)ROWS_TOT;
        double var  = sq[0] / (double)ROWS_TOT - mean*mean;
        double inv  = 1.0 / sqrt(var + 1e-5);
        double sc   = (double)g[o] * inv;
        g_s1[o] = (float)sc;
        g_t1[o] = (float)((double)bet[o] - mean*sc);
    }
}

__global__ void feat0_kernel()
{
    int idx = blockIdx.x*256 + threadIdx.x;
    if (idx >= BQ*C2) return;
    int o = idx & (C2-1);
    float sc = g_s1[o];
    float v = (sc >= 0.f) ? g_gmax[idx] : g_gmin[idx];
    g_feat0[idx] = v*sc + g_t1[o];
}

// ============================ fc GEMM ============================
__global__ __launch_bounds__(256) void gemm_kernel(const float* __restrict__ A,
                                                   const float* __restrict__ W,
                                                   const float* __restrict__ bias,
                                                   const float* __restrict__ ascale,
                                                   const float* __restrict__ ashift,
                                                   float* __restrict__ out,
                                                   int M, int Kd, int Nout, int do_relu)
{
    __shared__ __align__(16) float As[64*17];
    __shared__ __align__(16) float Bs[16*68];
    int tid = threadIdx.x, tx = tid & 15, ty = tid >> 4;
    int bn = blockIdx.x*64, bm = blockIdx.y*64;

    float acc[4][4];
    #pragma unroll
    for (int i = 0; i < 4; i++)
        #pragma unroll
        for (int j = 0; j < 4; j++) acc[i][j] = 0.f;

    for (int kt = 0; kt < Kd; kt += 16) {
        for (int idx = tid; idx < 1024; idx += 256) {
            int r = idx >> 4, c = idx & 15;
            int gr = bm + r, gc = kt + c;
            float v = 0.f;
            if (gr < M) {
                v = A[gr*Kd + gc];
                if (ascale) v = v*ascale[gc] + ashift[gc];
            }
            As[r*17 + c] = v;
        }
        for (int idx = tid; idx < 1024; idx += 256) {
            int n = idx >> 4, c = idx & 15;
            int gn = bn + n;
            Bs[c*68 + n] = (gn < Nout) ? W[gn*Kd + kt + c] : 0.f;
        }
        __syncthreads();
        #pragma unroll
        for (int c = 0; c < 16; c++) {
            float4 b4 = *(const float4*)&Bs[c*68 + tx*4];
            #pragma unroll
            for (int i = 0; i < 4; i++) {
                float a = As[(ty*4 + i)*17 + c];
                acc[i][0] += a * b4.x;
                acc[i][1] += a * b4.y;
                acc[i][2] += a * b4.z;
                acc[i][3] += a * b4.w;
            }
        }
        __syncthreads();
    }

    #pragma unroll
    for (int i = 0; i < 4; i++) {
        int row = bm + ty*4 + i;
        if (row >= M) continue;
        #pragma unroll
        for (int j = 0; j < 4; j++) {
            int col = bn + tx*4 + j;
            if (col >= Nout) continue;
            float v = acc[i][j] + bias[col];
            if (do_relu) v = fmaxf(v, 0.f);
            out[row*Nout + col] = v;
        }
    }
}

// ============================ column stats (parallel) ============================
__global__ __launch_bounds__(128) void colstats_kernel(const float* __restrict__ z,
                                                       const float* __restrict__ g,
                                                       const float* __restrict__ bet,
                                                       float* __restrict__ s_o, float* __restrict__ t_o,
                                                       int M, int C)
{
    __shared__ double ss[128], sq[128];
    int c = blockIdx.x, t = threadIdx.x;
    double s = 0.0, q = 0.0;
    for (int r = t; r < M; r += 128) {
        double v = (double)z[r*C + c];
        s += v; q += v*v;
    }
    ss[t] = s; sq[t] = q; __syncthreads();
    for (int st = 64; st; st >>= 1) {
        if (t < st) { ss[t] += ss[t+st]; sq[t] += sq[t+st]; }
        __syncthreads();
    }
    if (t == 0) {
        double mean = ss[0] / (double)M;
        double var  = sq[0] / (double)M - mean*mean;
        double inv  = 1.0 / sqrt(var + 1e-5);
        double sc   = (double)g[c] * inv;
        s_o[c] = (float)sc;
        t_o[c] = (float)((double)bet[c] - mean*sc);
    }
}

__global__ void tail_kernel(const float* __restrict__ normal,
                            const int* __restrict__ index,
                            float* __restrict__ out)
{
    int i = blockIdx.x*256 + threadIdx.x;
    if (i >= BQ*3) return;
    int q = i / 3, c = i - q*3;
    out[BQ*3 + i] = normal[(long)index[q]*3 + c];
}

// ============================ host ============================
extern "C" void kernel_launch(void* const* d_in, const int* in_sizes, int n_in,
                              void* d_out, int out_size)
{
    const float* pts    = (const float*)d_in[0];
    const float* normal = (const float*)d_in[1];
    const float* kpp    = (const float*)d_in[2];
    const float* kpw    = (const float*)d_in[3];
    const float* kps    = (const float*)d_in[4];
    const float* c1w    = (const float*)d_in[5];
    const float* c1b    = (const float*)d_in[6];
    const float* bn1g   = (const float*)d_in[7];
    const float* bn1b   = (const float*)d_in[8];
    const float* f1w    = (const float*)d_in[9];
    const float* f1b    = (const float*)d_in[10];
    const float* bn4g   = (const float*)d_in[11];
    const float* bn4b   = (const float*)d_in[12];
    const float* f2w    = (const float*)d_in[13];
    const float* f2b    = (const float*)d_in[14];
    const float* bn5g   = (const float*)d_in[15];
    const float* bn5b   = (const float*)d_in[16];
    const float* f3w    = (const float*)d_in[17];
    const float* f3b    = (const float*)d_in[18];
    const int*   index  = (const int*)d_in[19];
    float* out = (float*)d_out;

    void* p;
    cudaGetSymbolAddress(&p, g_feat0); float* feat0p = (float*)p;
    cudaGetSymbolAddress(&p, g_z1);    float* z1p = (float*)p;
    cudaGetSymbolAddress(&p, g_z2);    float* z2p = (float*)p;
    cudaGetSymbolAddress(&p, g_s4);    float* s4p = (float*)p;
    cudaGetSymbolAddress(&p, g_t4);    float* t4p = (float*)p;
    cudaGetSymbolAddress(&p, g_s5);    float* s5p = (float*)p;
    cudaGetSymbolAddress(&p, g_t5);    float* t5p = (float*)p;

    cudaFuncSetAttribute(conv1_kernel, cudaFuncAttributeMaxDynamicSharedMemorySize, CONV1_SMEM);

    // grid build
    zero_init_kernel<<<(GD3+255)/256, 256>>>();
    bbox_kernel<<<128, 256>>>(pts);
    wprep_kernel<<<256, 256>>>(c1w);
    bbox_fin_kernel<<<1, 32>>>();
    grid_count_kernel<<<(NPTS+255)/256, 256>>>(pts);
    prefixA_kernel<<<256, 256>>>();
    prefixB_kernel<<<1, 256>>>();
    prefixC_kernel<<<256, 256>>>();
    scatter_kernel<<<(NPTS+255)/256, 256>>>(pts);

    knn_grid_kernel<<<BQ, 256>>>(pts, index);
    kpconv_kernel<<<BQ, 128>>>(pts, kpp, kpw, kps, index);
    conv1_kernel<<<dim3(8, BQ), 256, CONV1_SMEM>>>(c1b);
    bn1_stats_kernel<<<C2, 128>>>(bn1g, bn1b);
    feat0_kernel<<<(BQ*C2 + 255)/256, 256>>>();

    gemm_kernel<<<dim3(8, 8), 256>>>(feat0p, f1w, f1b, nullptr, nullptr, z1p, BQ, 1024, 512, 1);
    colstats_kernel<<<512, 128>>>(z1p, bn4g, bn4b, s4p, t4p, BQ, 512);
    gemm_kernel<<<dim3(4, 8), 256>>>(z1p, f2w, f2b, s4p, t4p, z2p, BQ, 512, 256, 1);
    colstats_kernel<<<256, 128>>>(z2p, bn5g, bn5b, s5p, t5p, BQ, 256);
    gemm_kernel<<<dim3(1, 8), 256>>>(z2p, f3w, f3b, s5p, t5p, out, BQ, 256, 3, 0);

    tail_kernel<<<(BQ*3 + 255)/256, 256>>>(normal, index, out);
}

// round 15
// speedup vs baseline: 1.5890x; 1.5890x over previous
#include <cuda_runtime.h>
#include <cuda_bf16.h>
#include <math.h>

typedef unsigned long long ull;
typedef unsigned int uint;

#define NPTS 100000
#define BQ 500
#define KNN 100
#define C1 128
#define C2 1024
#define ROWS_TOT (BQ*KNN)
#define GD 64
#define GD3 (GD*GD*GD)
#define BCAP 512

// ---------------- scratch (device globals; no cudaMalloc allowed) ----------------
__device__ unsigned g_bbmin[3], g_bbmax[3];
__device__ float g_orig[3], g_w, g_winv;
__device__ int   g_cellcnt[GD3];
__device__ int   g_cellstart[GD3+1];
__device__ int   g_cellfill[GD3];
__device__ int   g_blocksum[256];
__device__ int   g_blockoff[257];
__device__ float4 g_spts[NPTS];
__device__ int   g_nbr[BQ*KNN];
__device__ uint  g_h1s[ROWS_TOT*C1];     // packed bf16: hi | (lo<<16)
__device__ uint  g_wfH[65536];           // W frag pool hi: [ot][ph][e]
__device__ uint  g_wfL[65536];           // W frag pool lo
__device__ float g_psum[BQ*C2];
__device__ float g_psumsq[BQ*C2];
__device__ float g_gmax[BQ*C2];
__device__ float g_gmin[BQ*C2];
__device__ float g_s1[C2], g_t1[C2];
__device__ float g_feat0[BQ*C2];
__device__ float g_z1[BQ*512];
__device__ float g_z2[BQ*256];
__device__ float g_s4[512], g_t4[512];
__device__ float g_s5[256], g_t5[256];

// ============================ grid build ============================
__device__ __forceinline__ unsigned enc_f(float f) {
    unsigned b = __float_as_uint(f);
    return (b & 0x80000000u) ? ~b : (b | 0x80000000u);
}
__device__ __forceinline__ float dec_f(unsigned u) {
    unsigned b = (u & 0x80000000u) ? (u ^ 0x80000000u) : ~u;
    return __uint_as_float(b);
}

__global__ void zero_init_kernel() {
    int i = blockIdx.x*256 + threadIdx.x;
    if (i < GD3) g_cellcnt[i] = 0;
    if (i < 3) { g_bbmin[i] = 0xFFFFFFFFu; g_bbmax[i] = 0u; }
}

__global__ __launch_bounds__(256) void bbox_kernel(const float* __restrict__ pts) {
    __shared__ unsigned smin[3][32], smax[3][32];
    unsigned lmin[3] = {0xFFFFFFFFu,0xFFFFFFFFu,0xFFFFFFFFu};
    unsigned lmax[3] = {0,0,0};
    for (int i = blockIdx.x*256 + threadIdx.x; i < NPTS; i += gridDim.x*256) {
        #pragma unroll
        for (int a = 0; a < 3; a++) {
            unsigned e = enc_f(pts[i*3+a]);
            lmin[a] = min(lmin[a], e); lmax[a] = max(lmax[a], e);
        }
    }
    int lane = threadIdx.x & 31, w = threadIdx.x >> 5;
    #pragma unroll
    for (int a = 0; a < 3; a++) {
        #pragma unroll
        for (int o = 16; o; o >>= 1) {
            lmin[a] = min(lmin[a], __shfl_xor_sync(0xFFFFFFFFu, lmin[a], o));
            lmax[a] = max(lmax[a], __shfl_xor_sync(0xFFFFFFFFu, lmax[a], o));
        }
        if (lane == 0) { smin[a][w] = lmin[a]; smax[a][w] = lmax[a]; }
    }
    __syncthreads();
    if (threadIdx.x < 3) {
        int a = threadIdx.x;
        unsigned mn = 0xFFFFFFFFu, mx = 0;
        for (int i = 0; i < 8; i++) { mn = min(mn, smin[a][i]); mx = max(mx, smax[a][i]); }
        atomicMin(&g_bbmin[a], mn);
        atomicMax(&g_bbmax[a], mx);
    }
}

__global__ void bbox_fin_kernel() {
    if (threadIdx.x == 0) {
        float rmax = 0.f;
        for (int a = 0; a < 3; a++) {
            float mn = dec_f(g_bbmin[a]), mx = dec_f(g_bbmax[a]);
            g_orig[a] = mn;
            rmax = fmaxf(rmax, mx - mn);
        }
        float w = rmax / (float)GD * 1.000002f + 1e-12f;
        g_w = w; g_winv = 1.f / w;
    }
}

__device__ __forceinline__ int cell_of(float x, float ox, float winv) {
    int i = (int)((x - ox) * winv);
    return min(max(i, 0), GD-1);
}

__global__ void grid_count_kernel(const float* __restrict__ pts) {
    int i = blockIdx.x*256 + threadIdx.x;
    if (i >= NPTS) return;
    float wi = g_winv;
    int ix = cell_of(pts[i*3+0], g_orig[0], wi);
    int iy = cell_of(pts[i*3+1], g_orig[1], wi);
    int iz = cell_of(pts[i*3+2], g_orig[2], wi);
    atomicAdd(&g_cellcnt[(iz*GD+iy)*GD+ix], 1);
}

__global__ __launch_bounds__(256) void prefixA_kernel() {
    __shared__ int red[256];
    int bk = blockIdx.x, t = threadIdx.x;
    int base = bk*1024 + t*4;
    int s = g_cellcnt[base] + g_cellcnt[base+1] + g_cellcnt[base+2] + g_cellcnt[base+3];
    red[t] = s; __syncthreads();
    for (int st = 128; st; st >>= 1) { if (t < st) red[t] += red[t+st]; __syncthreads(); }
    if (t == 0) g_blocksum[bk] = red[0];
}

__global__ __launch_bounds__(256) void prefixB_kernel() {
    __shared__ int sc[256];
    int t = threadIdx.x;
    sc[t] = g_blocksum[t]; __syncthreads();
    for (int off = 1; off < 256; off <<= 1) {
        int v = (t >= off) ? sc[t-off] : 0;
        __syncthreads();
        sc[t] += v;
        __syncthreads();
    }
    g_blockoff[t+1] = sc[t];
    if (t == 0) g_blockoff[0] = 0;
}

__global__ __launch_bounds__(256) void prefixC_kernel() {
    __shared__ int sc[256];
    int bk = blockIdx.x, t = threadIdx.x;
    int base = bk*1024 + t*4;
    int c0 = g_cellcnt[base], c1 = g_cellcnt[base+1], c2 = g_cellcnt[base+2], c3 = g_cellcnt[base+3];
    int tot = c0+c1+c2+c3;
    sc[t] = tot; __syncthreads();
    for (int off = 1; off < 256; off <<= 1) {
        int v = (t >= off) ? sc[t-off] : 0;
        __syncthreads();
        sc[t] += v;
        __syncthreads();
    }
    int run = g_blockoff[bk] + sc[t] - tot;
    g_cellstart[base] = run;   g_cellfill[base] = run;   run += c0;
    g_cellstart[base+1] = run; g_cellfill[base+1] = run; run += c1;
    g_cellstart[base+2] = run; g_cellfill[base+2] = run; run += c2;
    g_cellstart[base+3] = run; g_cellfill[base+3] = run;
    if (bk == 255 && t == 255) g_cellstart[GD3] = g_blockoff[256];
}

__global__ void scatter_kernel(const float* __restrict__ pts) {
    int i = blockIdx.x*256 + threadIdx.x;
    if (i >= NPTS) return;
    float x = pts[i*3+0], y = pts[i*3+1], z = pts[i*3+2];
    float wi = g_winv;
    int ix = cell_of(x, g_orig[0], wi);
    int iy = cell_of(y, g_orig[1], wi);
    int iz = cell_of(z, g_orig[2], wi);
    int pos = atomicAdd(&g_cellfill[(iz*GD+iy)*GD+ix], 1);
    if (pos >= 0 && pos < NPTS) g_spts[pos] = make_float4(x, y, z, __int_as_float(i));
}

// ============================ grid kNN (exact, L-inf) ============================
__constant__ int c_msched[13] = {0,1,2,3,4,6,8,11,16,22,31,44,63};

__global__ __launch_bounds__(256) void knn_grid_kernel(const float* __restrict__ pts,
                                                       const int* __restrict__ index)
{
    __shared__ unsigned hist[4096];
    __shared__ float bd_d[BCAP];
    __shared__ int   bd_i[BCAP];
    __shared__ int scnt[256];
    __shared__ int wred[8];
    __shared__ int s_T, s_cl, s_loPos, s_bdc, s_selc;
    __shared__ float qx, qy, qz;

    int b = blockIdx.x, tid = threadIdx.x;
    if (tid == 0) {
        int n = index[b];
        qx = pts[n*3+0]; qy = pts[n*3+1]; qz = pts[n*3+2];
    }
    for (int i = tid; i < 4096; i += 256) hist[i] = 0u;
    __syncthreads();

    float wi = g_winv;
    int cx = cell_of(qx, g_orig[0], wi);
    int cy = cell_of(qy, g_orig[1], wi);
    int cz = cell_of(qz, g_orig[2], wi);
    int wid = tid >> 5, lane = tid & 31;

    int m = 0;
    for (int si = 0; si < 13; si++) {
        m = c_msched[si];
        int zlo = max(cz-m,0), zhi = min(cz+m,GD-1);
        int ylo = max(cy-m,0), yhi = min(cy+m,GD-1);
        int xlo = max(cx-m,0), xhi = min(cx+m,GD-1);
        int yext = yhi-ylo+1;
        int R = (zhi-zlo+1)*yext;
        int cnt = 0;
        for (int r = tid; r < R; r += 256) {
            int z = zlo + r/yext, y = ylo + r%yext;
            int base = (z*GD+y)*GD;
            cnt += g_cellstart[base+xhi+1] - g_cellstart[base+xlo];
        }
        #pragma unroll
        for (int o = 16; o; o >>= 1) cnt += __shfl_xor_sync(0xFFFFFFFFu, cnt, o);
        if (lane == 0) wred[wid] = cnt;
        __syncthreads();
        if (tid == 0) {
            int s = 0;
            #pragma unroll
            for (int i = 0; i < 8; i++) s += wred[i];
            wred[0] = s;
        }
        __syncthreads();
        int total = wred[0];
        __syncthreads();
        bool full = (zlo==0 && zhi==GD-1 && ylo==0 && yhi==GD-1 && xlo==0 && xhi==GD-1);
        if (total >= KNN || full) break;
    }
    int mh = m + 1;
    int zlo = max(cz-mh,0), zhi = min(cz+mh,GD-1);
    int ylo = max(cy-mh,0), yhi = min(cy+mh,GD-1);
    int xlo = max(cx-mh,0), xhi = min(cx+mh,GD-1);
    int yext = yhi-ylo+1;
    int R = (zhi-zlo+1)*yext;

    for (int r = wid; r < R; r += 8) {
        int z = zlo + r/yext, y = ylo + r%yext;
        int base = (z*GD+y)*GD;
        int lo = g_cellstart[base+xlo], hi = g_cellstart[base+xhi+1];
        lo = min(max(lo, 0), NPTS); hi = min(max(hi, lo), NPTS);
        for (int t = lo + lane; t < hi; t += 32) {
            float4 p = g_spts[t];
            float d = fmaxf(fmaxf(fabsf(p.x-qx), fabsf(p.y-qy)), fabsf(p.z-qz));
            unsigned bin = __float_as_uint(d) >> 19;
            if (bin > 4095u) bin = 4095u;
            atomicAdd(&hist[bin], 1u);
        }
    }
    __syncthreads();

    {
        unsigned s = 0;
        #pragma unroll
        for (int j = 0; j < 16; j++) s += hist[tid*16 + j];
        scnt[tid] = (int)s;
    }
    __syncthreads();
    if (tid == 0) {
        int cum = 0, si = 0;
        while (si < 255 && cum + scnt[si] < KNN) { cum += scnt[si]; si++; }
        int t = si*16;
        for (; t < 4095; t++) {
            int h = (int)hist[t];
            if (cum + h >= KNN) break;
            cum += h;
        }
        s_T = t; s_cl = cum;
        s_loPos = 0; s_bdc = 0; s_selc = cum;
    }
    __syncthreads();
    int T = s_T, cl = s_cl;

    for (int r = wid; r < R; r += 8) {
        int z = zlo + r/yext, y = ylo + r%yext;
        int base = (z*GD+y)*GD;
        int lo = g_cellstart[base+xlo], hi = g_cellstart[base+xhi+1];
        lo = min(max(lo, 0), NPTS); hi = min(max(hi, lo), NPTS);
        for (int t = lo + lane; t < hi; t += 32) {
            float4 p = g_spts[t];
            float d = fmaxf(fmaxf(fabsf(p.x-qx), fabsf(p.y-qy)), fabsf(p.z-qz));
            unsigned bin = __float_as_uint(d) >> 19;
            if (bin > 4095u) bin = 4095u;
            int bi = (int)bin;
            if (bi < T) {
                int ppos = atomicAdd(&s_loPos, 1);
                if (ppos < KNN) g_nbr[b*KNN + ppos] = __float_as_int(p.w);
            } else if (bi == T) {
                int ppos = atomicAdd(&s_bdc, 1);
                if (ppos < BCAP) { bd_d[ppos] = d; bd_i[ppos] = __float_as_int(p.w); }
            }
        }
    }
    __syncthreads();

    int need = KNN - cl;
    int c = s_bdc < BCAP ? s_bdc : BCAP;
    for (int i = tid; i < c; i += 256) {
        float di = bd_d[i];
        int   ni = bd_i[i];
        int rank = 0;
        for (int j = 0; j < c; j++) {
            float dj = bd_d[j];
            rank += (dj < di) || (dj == di && bd_i[j] < ni);
        }
        if (rank < need) {
            int pp = atomicAdd(&s_selc, 1);
            if (pp < KNN) g_nbr[b*KNN + pp] = ni;
        }
    }
}

// ============================ bf16 helpers ============================
__device__ __forceinline__ unsigned short bf16_bits(float f) {
    __nv_bfloat16 h = __float2bfloat16(f);
    return *reinterpret_cast<unsigned short*>(&h);
}
__device__ __forceinline__ float bf16_val(unsigned short u) {
    __nv_bfloat16 h = *reinterpret_cast<__nv_bfloat16*>(&u);
    return __bfloat162float(h);
}

// ============================ KPConv (emits packed hi|lo bf16) ============================
__global__ __launch_bounds__(128) void kpconv_kernel(const float* __restrict__ pts,
                                                     const float* __restrict__ kp_points,
                                                     const float* __restrict__ kp_weights,
                                                     const float* __restrict__ kp_sigma,
                                                     const int* __restrict__ index)
{
    __shared__ float kpw_s[48*128];
    __shared__ float v_s[100*48];
    __shared__ float rel_s[100][3];
    __shared__ float w_s[100][16];
    __shared__ float sel[3];
    __shared__ float kpp_s[15][3];

    int b = blockIdx.x;
    int tid = threadIdx.x;

    for (int idx = tid; idx < 48*128; idx += 128) {
        int j = idx >> 7, o = idx & 127;
        kpw_s[idx] = (j < 45) ? kp_weights[j*128 + o] : 0.f;
    }
    if (tid < 3) sel[tid] = pts[(long)index[b]*3 + tid];
    if (tid < 45) kpp_s[tid/3][tid%3] = kp_points[tid];
    __syncthreads();

    if (tid < 100) {
        int n = g_nbr[b*KNN + tid];
        n = min(max(n, 0), NPTS-1);
        rel_s[tid][0] = pts[n*3+0] - sel[0];
        rel_s[tid][1] = pts[n*3+1] - sel[1];
        rel_s[tid][2] = pts[n*3+2] - sel[2];
    }
    __syncthreads();

    float sg = kp_sigma[0];
    float inv2 = -0.5f / (sg*sg);

    for (int idx = tid; idx < 100*16; idx += 128) {
        int k = idx >> 4, p = idx & 15;
        float val = 0.f;
        if (p < 15) {
            float dx = rel_s[k][0] - kpp_s[p][0];
            float dy = rel_s[k][1] - kpp_s[p][1];
            float dz = rel_s[k][2] - kpp_s[p][2];
            val = __expf(inv2 * (dx*dx + dy*dy + dz*dz));
        }
        w_s[k][p] = val;
    }
    __syncthreads();

    for (int idx = tid; idx < 100*48; idx += 128) {
        int k = idx / 48, j = idx - k*48;
        float val = 0.f;
        if (j < 45) {
            int p = j / 3, ch = j - p*3;
            val = rel_s[k][ch] * w_s[k][p];
        }
        v_s[idx] = val;
    }
    __syncthreads();

    int o = tid;
    float kw[48];
    #pragma unroll
    for (int j = 0; j < 48; j++) kw[j] = kpw_s[j*128 + o];

    for (int k = 0; k < KNN; k++) {
        const float4* vp = (const float4*)&v_s[k*48];
        float a0 = 0.f, a1 = 0.f, a2 = 0.f, a3 = 0.f;
        #pragma unroll
        for (int j4 = 0; j4 < 12; j4++) {
            float4 v4 = vp[j4];
            a0 += v4.x * kw[j4*4+0];
            a1 += v4.y * kw[j4*4+1];
            a2 += v4.z * kw[j4*4+2];
            a3 += v4.w * kw[j4*4+3];
        }
        float v = fmaxf((a0+a1) + (a2+a3), 0.f);
        unsigned short hi = bf16_bits(v);
        unsigned short lo = bf16_bits(v - bf16_val(hi));
        g_h1s[(b*KNN + k)*C1 + o] = (uint)hi | ((uint)lo << 16);
    }
}

// ============ W fragment precompute (once; frag-ordered global pools) ============
__global__ void wprep_kernel(const float* __restrict__ W) {
    int e2 = blockIdx.x*256 + threadIdx.x;
    if (e2 >= 65536) return;
    int ot = e2 >> 13, rem = e2 & 8191;
    int ph = rem >> 12, e = rem & 4095;
    int R = e & 1, L = (e >> 1) & 31, N = (e >> 6) & 15, K = e >> 10;
    int n = N*8 + (L >> 2);
    int k = ph*64 + K*16 + (L & 3)*2 + R*8;
    const float* wp = &W[((size_t)(ot*128 + n))*C1 + k];
    float f0 = wp[0], f1 = wp[1];
    unsigned short h0 = bf16_bits(f0), h1 = bf16_bits(f1);
    g_wfH[e2] = (uint)h0 | ((uint)h1 << 16);
    unsigned short l0 = bf16_bits(f0 - bf16_val(h0));
    unsigned short l1 = bf16_bits(f1 - bf16_val(h1));
    g_wfL[e2] = (uint)l0 | ((uint)l1 << 16);
}

// ======== conv1 v8 (measured-best): mma.sync bf16-split, per-term loop ========
#define OFF_AL   16384
#define OFF_WH   32768
#define OFF_WL   49152
#define OFF_PART 66560
#define OFF_BIAS 70656
#define CONV1_SMEM 71168
#define STG_LD 130

__global__ __launch_bounds__(256) void conv1_kernel(const float* __restrict__ bias)
{
    extern __shared__ char smc[];
    uint* AH = (uint*)smc;
    uint* AL = (uint*)(smc + OFF_AL);
    uint* WH = (uint*)(smc + OFF_WH);
    uint* WL = (uint*)(smc + OFF_WL);
    float* sbias = (float*)(smc + OFF_BIAS);

    int ot = blockIdx.x, b = blockIdx.y;
    int tid = threadIdx.x, lane = tid & 31, wid = tid >> 5;

    if (tid < 128) sbias[tid] = bias[ot*128 + tid];

    float acc[16][4];
    #pragma unroll
    for (int nt = 0; nt < 16; nt++)
        #pragma unroll
        for (int r = 0; r < 4; r++) acc[nt][r] = 0.f;

    for (int ph = 0; ph < 2; ph++) {
        if (ph) __syncthreads();

        // ---- A pack: 2 LDG.32 + bit-permute per element ----
        for (int e = tid; e < 4096; e += 256) {
            int R = e & 3, L = (e >> 2) & 31, M = (e >> 7) & 7, K = e >> 10;
            int row = M*16 + (L >> 2) + (R & 1)*8;
            int k   = ph*64 + K*16 + (L & 3)*2 + ((R >> 1) & 1)*8;
            uint s0 = 0, s1 = 0;
            if (row < KNN) {
                const uint* hp = &g_h1s[((size_t)b*KNN + row)*C1 + k];
                s0 = hp[0]; s1 = hp[1];
            }
            AH[e] = (s0 & 0xFFFFu) | (s1 << 16);
            AL[e] = (s0 >> 16) | (s1 & 0xFFFF0000u);
        }
        // ---- W fill: straight uint4 copy from precomputed pools ----
        {
            int wbase = (ot*2 + ph) << 12;
            const uint4* srcH = (const uint4*)&g_wfH[wbase];
            const uint4* srcL = (const uint4*)&g_wfL[wbase];
            uint4* dstH = (uint4*)WH;
            uint4* dstL = (uint4*)WL;
            for (int i = tid; i < 1024; i += 256) {
                dstH[i] = srcH[i];
                dstL[i] = srcL[i];
            }
        }
        __syncthreads();

        // ---- MMA: warp wid owns m-tile wid, all 16 n-tiles; 3 split terms ----
        #pragma unroll
        for (int p = 0; p < 3; p++) {
            const uint* Ab = (p == 1) ? AL : AH;
            const uint* Bb = (p == 2) ? WL : WH;
            #pragma unroll
            for (int ks = 0; ks < 4; ks++) {
                uint4 a = *(const uint4*)&Ab[(((ks*8 + wid)*32) + lane)*4];
                #pragma unroll
                for (int nt = 0; nt < 16; nt++) {
                    uint2 bf = *(const uint2*)&Bb[(((ks*16 + nt)*32) + lane)*2];
                    asm volatile(
                        "mma.sync.aligned.m16n8k16.row.col.f32.bf16.bf16.f32 "
                        "{%0,%1,%2,%3}, {%4,%5,%6,%7}, {%8,%9}, {%0,%1,%2,%3};"
                        : "+f"(acc[nt][0]), "+f"(acc[nt][1]), "+f"(acc[nt][2]), "+f"(acc[nt][3])
                        : "r"(a.x), "r"(a.y), "r"(a.z), "r"(a.w), "r"(bf.x), "r"(bf.y));
                }
            }
        }
    }
    __syncthreads();

    // ---- stage relu(D + bias) into smem [col][row] (reuses frag space) ----
    float* stage = (float*)smc;
    {
        int g = lane >> 2, tg = lane & 3;
        int r0 = wid*16 + g, r1 = r0 + 8;
        #pragma unroll
        for (int nt = 0; nt < 16; nt++) {
            int c0 = nt*8 + tg*2;
            stage[c0*STG_LD + r0]     = fmaxf(acc[nt][0] + sbias[c0], 0.f);
            stage[(c0+1)*STG_LD + r0] = fmaxf(acc[nt][1] + sbias[c0+1], 0.f);
            stage[c0*STG_LD + r1]     = fmaxf(acc[nt][2] + sbias[c0], 0.f);
            stage[(c0+1)*STG_LD + r1] = fmaxf(acc[nt][3] + sbias[c0+1], 0.f);
        }
    }
    __syncthreads();

    // ---- column stats over rows 0..99 (2 threads per column) ----
    float* part = (float*)(smc + OFF_PART);
    {
        int col = tid >> 1, half = tid & 1;
        float mx = -1e30f, mn = 1e30f, s = 0.f, q = 0.f;
        int rbeg = half*50;
        #pragma unroll 10
        for (int r = rbeg; r < rbeg + 50; r++) {
            float v = stage[col*STG_LD + r];
            mx = fmaxf(mx, v); mn = fminf(mn, v);
            s += v; q += v*v;
        }
        part[0*256 + tid] = mx;
        part[1*256 + tid] = mn;
        part[2*256 + tid] = s;
        part[3*256 + tid] = q;
    }
    __syncthreads();
    if (tid < 128) {
        int e = tid*2;
        int o = b*C2 + ot*128 + tid;
        g_gmax[o]   = fmaxf(part[0*256 + e], part[0*256 + e + 1]);
        g_gmin[o]   = fminf(part[1*256 + e], part[1*256 + e + 1]);
        g_psum[o]   = part[2*256 + e] + part[2*256 + e + 1];
        g_psumsq[o] = part[3*256 + e] + part[3*256 + e + 1];
    }
}

// ============================ BN1 stats (parallel) ============================
__global__ __launch_bounds__(128) void bn1_stats_kernel(const float* __restrict__ g,
                                                        const float* __restrict__ bet)
{
    __shared__ double ss[128], sq[128];
    int o = blockIdx.x, t = threadIdx.x;
    double s = 0.0, q = 0.0;
    for (int b = t; b < BQ; b += 128) {
        s += (double)g_psum[b*C2 + o];
        q += (double)g_psumsq[b*C2 + o];
    }
    ss[t] = s; sq[t] = q; __syncthreads();
    for (int st = 64; st; st >>= 1) {
        if (t < st) { ss[t] += ss[t+st]; sq[t] += sq[t+st]; }
        __syncthreads();
    }
    if (t == 0) {
        double mean = ss[0] / (double)ROWS_TOT;
        double var  = sq[0] / (double)ROWS_TOT - mean*mean;
        double inv  = 1.0 / sqrt(var + 1e-5);
        double sc   = (double)g[o] * inv;
        g_s1[o] = (float)sc;
        g_t1[o] = (float)((double)bet[o] - mean*sc);
    }
}

__global__ void feat0_kernel()
{
    int idx = blockIdx.x*256 + threadIdx.x;
    if (idx >= BQ*C2) return;
    int o = idx & (C2-1);
    float sc = g_s1[o];
    float v = (sc >= 0.f) ? g_gmax[idx] : g_gmin[idx];
    g_feat0[idx] = v*sc + g_t1[o];
}

// ============================ fc GEMM ============================
__global__ __launch_bounds__(256) void gemm_kernel(const float* __restrict__ A,
                                                   const float* __restrict__ W,
                                                   const float* __restrict__ bias,
                                                   const float* __restrict__ ascale,
                                                   const float* __restrict__ ashift,
                                                   float* __restrict__ out,
                                                   int M, int Kd, int Nout, int do_relu)
{
    __shared__ __align__(16) float As[64*17];
    __shared__ __align__(16) float Bs[16*68];
    int tid = threadIdx.x, tx = tid & 15, ty = tid >> 4;
    int bn = blockIdx.x*64, bm = blockIdx.y*64;

    float acc[4][4];
    #pragma unroll
    for (int i = 0; i < 4; i++)
        #pragma unroll
        for (int j = 0; j < 4; j++) acc[i][j] = 0.f;

    for (int kt = 0; kt < Kd; kt += 16) {
        for (int idx = tid; idx < 1024; idx += 256) {
            int r = idx >> 4, c = idx & 15;
            int gr = bm + r, gc = kt + c;
            float v = 0.f;
            if (gr < M) {
                v = A[gr*Kd + gc];
                if (ascale) v = v*ascale[gc] + ashift[gc];
            }
            As[r*17 + c] = v;
        }
        for (int idx = tid; idx < 1024; idx += 256) {
            int n = idx >> 4, c = idx & 15;
            int gn = bn + n;
            Bs[c*68 + n] = (gn < Nout) ? W[gn*Kd + kt + c] : 0.f;
        }
        __syncthreads();
        #pragma unroll
        for (int c = 0; c < 16; c++) {
            float4 b4 = *(const float4*)&Bs[c*68 + tx*4];
            #pragma unroll
            for (int i = 0; i < 4; i++) {
                float a = As[(ty*4 + i)*17 + c];
                acc[i][0] += a * b4.x;
                acc[i][1] += a * b4.y;
                acc[i][2] += a * b4.z;
                acc[i][3] += a * b4.w;
            }
        }
        __syncthreads();
    }

    #pragma unroll
    for (int i = 0; i < 4; i++) {
        int row = bm + ty*4 + i;
        if (row >= M) continue;
        #pragma unroll
        for (int j = 0; j < 4; j++) {
            int col = bn + tx*4 + j;
            if (col >= Nout) continue;
            float v = acc[i][j] + bias[col];
            if (do_relu) v = fmaxf(v, 0.f);
            out[row*Nout + col] = v;
        }
    }
}

// ============================ column stats (parallel) ============================
__global__ __launch_bounds__(128) void colstats_kernel(const float* __restrict__ z,
                                                       const float* __restrict__ g,
                                                       const float* __restrict__ bet,
                                                       float* __restrict__ s_o, float* __restrict__ t_o,
                                                       int M, int C)
{
    __shared__ double ss[128], sq[128];
    int c = blockIdx.x, t = threadIdx.x;
    double s = 0.0, q = 0.0;
    for (int r = t; r < M; r += 128) {
        double v = (double)z[r*C + c];
        s += v; q += v*v;
    }
    ss[t] = s; sq[t] = q; __syncthreads();
    for (int st = 64; st; st >>= 1) {
        if (t < st) { ss[t] += ss[t+st]; sq[t] += sq[t+st]; }
        __syncthreads();
    }
    if (t == 0) {
        double mean = ss[0] / (double)M;
        double var  = sq[0] / (double)M - mean*mean;
        double inv  = 1.0 / sqrt(var + 1e-5);
        double sc   = (double)g[c] * inv;
        s_o[c] = (float)sc;
        t_o[c] = (float)((double)bet[c] - mean*sc);
    }
}

__global__ void tail_kernel(const float* __restrict__ normal,
                            const int* __restrict__ index,
                            float* __restrict__ out)
{
    int i = blockIdx.x*256 + threadIdx.x;
    if (i >= BQ*3) return;
    int q = i / 3, c = i - q*3;
    out[BQ*3 + i] = normal[(long)index[q]*3 + c];
}

// ============================ host ============================
extern "C" void kernel_launch(void* const* d_in, const int* in_sizes, int n_in,
                              void* d_out, int out_size)
{
    const float* pts    = (const float*)d_in[0];
    const float* normal = (const float*)d_in[1];
    const float* kpp    = (const float*)d_in[2];
    const float* kpw    = (const float*)d_in[3];
    const float* kps    = (const float*)d_in[4];
    const float* c1w    = (const float*)d_in[5];
    const float* c1b    = (const float*)d_in[6];
    const float* bn1g   = (const float*)d_in[7];
    const float* bn1b   = (const float*)d_in[8];
    const float* f1w    = (const float*)d_in[9];
    const float* f1b    = (const float*)d_in[10];
    const float* bn4g   = (const float*)d_in[11];
    const float* bn4b   = (const float*)d_in[12];
    const float* f2w    = (const float*)d_in[13];
    const float* f2b    = (const float*)d_in[14];
    const float* bn5g   = (const float*)d_in[15];
    const float* bn5b   = (const float*)d_in[16];
    const float* f3w    = (const float*)d_in[17];
    const float* f3b    = (const float*)d_in[18];
    const int*   index  = (const int*)d_in[19];
    float* out = (float*)d_out;

    void* p;
    cudaGetSymbolAddress(&p, g_feat0); float* feat0p = (float*)p;
    cudaGetSymbolAddress(&p, g_z1);    float* z1p = (float*)p;
    cudaGetSymbolAddress(&p, g_z2);    float* z2p = (float*)p;
    cudaGetSymbolAddress(&p, g_s4);    float* s4p = (float*)p;
    cudaGetSymbolAddress(&p, g_t4);    float* t4p = (float*)p;
    cudaGetSymbolAddress(&p, g_s5);    float* s5p = (float*)p;
    cudaGetSymbolAddress(&p, g_t5);    float* t5p = (float*)p;

    cudaFuncSetAttribute(conv1_kernel, cudaFuncAttributeMaxDynamicSharedMemorySize, CONV1_SMEM);

    // grid build
    zero_init_kernel<<<(GD3+255)/256, 256>>>();
    bbox_kernel<<<128, 256>>>(pts);
    wprep_kernel<<<256, 256>>>(c1w);
    bbox_fin_kernel<<<1, 32>>>();
    grid_count_kernel<<<(NPTS+255)/256, 256>>>(pts);
    prefixA_kernel<<<256, 256>>>();
    prefixB_kernel<<<1, 256>>>();
    prefixC_kernel<<<256, 256>>>();
    scatter_kernel<<<(NPTS+255)/256, 256>>>(pts);

    knn_grid_kernel<<<BQ, 256>>>(pts, index);
    kpconv_kernel<<<BQ, 128>>>(pts, kpp, kpw, kps, index);
    conv1_kernel<<<dim3(8, BQ), 256, CONV1_SMEM>>>(c1b);
    bn1_stats_kernel<<<C2, 128>>>(bn1g, bn1b);
    feat0_kernel<<<(BQ*C2 + 255)/256, 256>>>();

    gemm_kernel<<<dim3(8, 8), 256>>>(feat0p, f1w, f1b, nullptr, nullptr, z1p, BQ, 1024, 512, 1);
    colstats_kernel<<<512, 128>>>(z1p, bn4g, bn4b, s4p, t4p, BQ, 512);
    gemm_kernel<<<dim3(4, 8), 256>>>(z1p, f2w, f2b, s4p, t4p, z2p, BQ, 512, 256, 1);
    colstats_kernel<<<256, 128>>>(z2p, bn5g, bn5b, s5p, t5p, BQ, 256);
    gemm_kernel<<<dim3(1, 8), 256>>>(z2p, f3w, f3b, s5p, t5p, out, BQ, 256, 3, 0);

    tail_kernel<<<(BQ*3 + 255)/256, 256>>>(normal, index, out);
}